// round 15
// baseline (speedup 1.0000x reference)
#include <cuda_runtime.h>
#include <cuda_fp16.h>
#include <mma.h>
#include <cstdint>

using namespace nvcuda;

// Problem constants
#define N_NODES 50000
#define N_EDGES 1600000
#define IN_DIM  512
#define OUT_DIM 256
#define DEG_CAP 128      // P(degree > 128) ~ 0 for Binomial(1.6M, 1/50K)

#define M_PAD   50048    // 391 * 128

// Pre-converted A (inputs) in fp16: [M_PAD, 512] (51.2 MB)
__device__ static __half g_Ah16[(size_t)M_PAD * IN_DIM];

// Scratch: support = inputs @ weight, [N_NODES, OUT_DIM] in FP16 (25.6 MB)
__device__ static __half g_support[(size_t)N_NODES * OUT_DIM];

// Pre-converted B (weight): fp16 (global staging).
#define B_LDM 272
__device__ static __half g_Bh[(size_t)IN_DIM * B_LDM];

// Padded CSR
__device__ static int   g_counts[N_NODES];
__device__ static int2  g_edge[(size_t)N_NODES * DEG_CAP];   // .x=col,.y=val bits

// ---------------------------------------------------------------------------
// cp.async helpers (sm_80+ base PTX)
// ---------------------------------------------------------------------------
__device__ __forceinline__ void cp_async16(void* sptr, const void* gptr) {
    uint32_t s = (uint32_t)__cvta_generic_to_shared(sptr);
    asm volatile("cp.async.cg.shared.global [%0], [%1], 16;" :: "r"(s), "l"(gptr));
}
#define CP_COMMIT()  asm volatile("cp.async.commit_group;" ::: "memory")
#define CP_WAIT(N)   asm volatile("cp.async.wait_group %0;" :: "n"(N) : "memory")

// ---------------------------------------------------------------------------
// A pre-convert: f32 -> fp16, rows >= N_NODES zeroed.
// One float4 -> 4 halves (8B) per thread per iteration.
// ---------------------------------------------------------------------------
#define CA_TOTAL_F4 ((size_t)M_PAD * IN_DIM / 4)   // 6,406,144
__global__ __launch_bounds__(256) void convert_A_kernel(const float* __restrict__ A)
{
    const size_t u = (size_t)blockIdx.x * 256 + threadIdx.x;
    if (u >= CA_TOTAL_F4) return;
    const size_t row = u / (IN_DIM / 4);
    uint2 hp = make_uint2(0u, 0u);
    if (row < N_NODES) {
        const float4 v = *reinterpret_cast<const float4*>(A + u * 4);
        __half2 p0 = __floats2half2_rn(v.x, v.y);
        __half2 p1 = __floats2half2_rn(v.z, v.w);
        hp.x = *reinterpret_cast<uint32_t*>(&p0);
        hp.y = *reinterpret_cast<uint32_t*>(&p1);
    }
    *reinterpret_cast<uint2*>(g_Ah16 + u * 4) = hp;
}

// ---------------------------------------------------------------------------
// B pre-convert: f32 -> fp16.
// ---------------------------------------------------------------------------
__global__ __launch_bounds__(256) void convert_B_kernel(const float* __restrict__ B)
{
    const int k = blockIdx.x;
    const int n = threadIdx.x;
    g_Bh[(size_t)k * B_LDM + n] = __float2half_rn(B[(size_t)k * OUT_DIM + n]);
    if (n < B_LDM - OUT_DIM)
        g_Bh[(size_t)k * B_LDM + OUT_DIM + n] = __float2half_rn(0.f);
}

// ---------------------------------------------------------------------------
// GEMM: pure fp16 WMMA, cp.async ring-3 for BOTH A and B. No conversion,
// no register prefetch. CTA 128x256, 512 threads, warp tile 32x64. KC=64.
// ---------------------------------------------------------------------------
#define GM_BM    128
#define GM_KC    64
#define GM_NCH   (IN_DIM / GM_KC)       // 8
#define A_LDM    72                     // 144 B row stride (mod 128 = 16)
#define B_SLD    264                    // 528 B row stride (mod 128 = 16)
#define A_ELEMS  (GM_BM * A_LDM)        // 9216 halves / buffer (18432 B)
#define BS_ELEMS (GM_KC * B_SLD)        // 16896 halves / buffer (33792 B)
#define GM_SMEM  ((3 * A_ELEMS + 3 * BS_ELEMS) * 2)   // 156672 B

__global__ __launch_bounds__(512, 1) void gemm_fp16_kernel(
    __half* __restrict__ C)
{
    extern __shared__ __align__(16) char smem[];
    __half* Aring = reinterpret_cast<__half*>(smem);
    __half* Bring = Aring + 3 * A_ELEMS;

    const int tid  = threadIdx.x;
    const int wid  = tid >> 5;
    const int lane = tid & 31;
    const int wm   = wid >> 2;
    const int wn   = wid & 3;
    const int mbase = blockIdx.x * GM_BM;

    // A: 128 rows x 8 x 16B units = 1024 units; 2/thread.
    // B: 64 rows x 32 x 16B units = 2048 units; 4/thread.
    const int a_row = tid >> 3;           // with +64 per it: 0..127
    const int a_c   = tid & 7;            // 0..7
    const int b_row = tid >> 5;           // 0..15 (+16 per it)
    const int b_c4  = tid & 31;           // 0..31

    wmma::fragment<wmma::accumulator, 16, 16, 16, float> acc[2][4];
#pragma unroll
    for (int i = 0; i < 2; i++)
#pragma unroll
        for (int j = 0; j < 4; j++) wmma::fill_fragment(acc[i][j], 0.0f);

    auto issue_chunk = [&](int ch, int buf) {
        __half* Ab = Aring + buf * A_ELEMS;
        __half* Bb = Bring + buf * BS_ELEMS;
        // A fp16 from g_Ah16 (always in-bounds: mbase+row <= 50047 < M_PAD)
#pragma unroll
        for (int it = 0; it < 2; it++) {
            const int r = a_row + 64 * it;
            cp_async16(Ab + r * A_LDM + a_c * 8,
                       g_Ah16 + (size_t)(mbase + r) * IN_DIM + ch * GM_KC + a_c * 8);
        }
#pragma unroll
        for (int it = 0; it < 4; it++) {
            const int r = b_row + 16 * it;
            cp_async16(Bb + r * B_SLD + b_c4 * 8,
                       g_Bh + (size_t)(ch * GM_KC + r) * B_LDM + b_c4 * 8);
        }
    };

    // ---- prologue: two chunks in flight ----
    issue_chunk(0, 0); CP_COMMIT();
    issue_chunk(1, 1); CP_COMMIT();
    CP_WAIT(1);                           // chunk 0 resident
    __syncthreads();

    for (int ch = 0; ch < GM_NCH; ch++) {
        // issue chunk ch+2 into buffer (ch+2)%3 (free since compute(ch-1) done)
        if (ch + 2 < GM_NCH) issue_chunk(ch + 2, (ch + 2) % 3);
        CP_COMMIT();                      // empty groups at tail keep count aligned

        // ---- compute chunk ch ----
        const __half* Acur = Aring + (ch % 3) * A_ELEMS;
        const __half* Bcur = Bring + (ch % 3) * BS_ELEMS;
#pragma unroll
        for (int ks = 0; ks < GM_KC / 16; ks++) {
            wmma::fragment<wmma::matrix_a, 16, 16, 16, __half, wmma::row_major> ah[2];
#pragma unroll
            for (int i = 0; i < 2; i++) {
                const int ar = wm * 32 + i * 16;
                wmma::load_matrix_sync(ah[i], Acur + ar * A_LDM + ks * 16, A_LDM);
            }
#pragma unroll
            for (int j = 0; j < 4; j++) {
                const int nc = wn * 64 + j * 16;
                wmma::fragment<wmma::matrix_b, 16, 16, 16, __half, wmma::row_major> bf;
                wmma::load_matrix_sync(bf, Bcur + ks * 16 * B_SLD + nc, B_SLD);
#pragma unroll
                for (int i = 0; i < 2; i++)
                    wmma::mma_sync(acc[i][j], ah[i], bf, acc[i][j]);
            }
        }

        CP_WAIT(1);                       // chunk ch+1 resident
        __syncthreads();                  // all warps done with buffer ch
    }

    // ---- epilogue: stage f32 tiles in smem, convert to fp16, store ----
    float* stage = reinterpret_cast<float*>(smem) + wid * 256;   // 16 KB
    const int lr = lane >> 1;
    const int lc = (lane & 1) * 8;

#pragma unroll
    for (int i = 0; i < 2; i++) {
        const int r0 = mbase + wm * 32 + i * 16;
        const bool ok = (r0 + 16 <= N_NODES);
#pragma unroll
        for (int j = 0; j < 4; j++) {
            wmma::store_matrix_sync(stage, acc[i][j], 16, wmma::mem_row_major);
            __syncwarp();
            if (ok) {
                const int c0 = wn * 64 + j * 16;
                const float* sp = stage + lr * 16 + lc;
                __half2 hh[4];
#pragma unroll
                for (int q = 0; q < 4; q++)
                    hh[q] = __floats2half2_rn(sp[2 * q], sp[2 * q + 1]);
                *reinterpret_cast<uint4*>(
                    &C[(size_t)(r0 + lr) * OUT_DIM + c0 + lc]) =
                    *reinterpret_cast<uint4*>(hh);
            }
            __syncwarp();
        }
    }
}

// ---------------------------------------------------------------------------
// Padded-CSR build (side stream)
// ---------------------------------------------------------------------------
__global__ __launch_bounds__(256) void zero_counts_kernel()
{
    int i = blockIdx.x * 256 + threadIdx.x;
    if (i < N_NODES) g_counts[i] = 0;
}

__global__ __launch_bounds__(256) void scatter_kernel(
    const int* __restrict__ rows,
    const int* __restrict__ cols,
    const float* __restrict__ vals)
{
    int e = blockIdx.x * 256 + threadIdx.x;
    if (e >= N_EDGES) return;
    const int r = rows[e];
    int pos = atomicAdd(&g_counts[r], 1);
    if (pos < DEG_CAP)
        g_edge[(size_t)r * DEG_CAP + pos] = make_int2(cols[e], __float_as_int(vals[e]));
}

// ---------------------------------------------------------------------------
// SpMM over padded CSR, FP16 support gathers, unroll 8 (R10-proven).
// CTA = 256 threads = 8 rows x 32 lanes; lane owns 8 columns (uint4).
// ---------------------------------------------------------------------------
__global__ __launch_bounds__(256) void spmm_csr_kernel(
    const float* __restrict__ bias,
    float* __restrict__ out)
{
    const int g = threadIdx.x >> 5;
    const int lane = threadIdx.x & 31;
    const int row = blockIdx.x * 8 + g;      // 50000 = 8 * 6250

    const int2* __restrict__ seg = g_edge + (size_t)row * DEG_CAP;
    int cnt = g_counts[row];
    if (cnt > DEG_CAP) cnt = DEG_CAP;

    const uint4* __restrict__ sup4 = reinterpret_cast<const uint4*>(g_support);

    float acc[8];
    {
        const float4 b0 = __ldg(reinterpret_cast<const float4*>(bias) + lane * 2);
        const float4 b1 = __ldg(reinterpret_cast<const float4*>(bias) + lane * 2 + 1);
        acc[0] = b0.x; acc[1] = b0.y; acc[2] = b0.z; acc[3] = b0.w;
        acc[4] = b1.x; acc[5] = b1.y; acc[6] = b1.z; acc[7] = b1.w;
    }

#define ACC_EDGE(qv, vv) do {                                                 \
        const __half2* _h = reinterpret_cast<const __half2*>(&(qv));          \
        _Pragma("unroll")                                                     \
        for (int _k = 0; _k < 4; _k++) {                                      \
            const float2 _f = __half22float2(_h[_k]);                         \
            acc[2 * _k + 0] = fmaf((vv), _f.x, acc[2 * _k + 0]);              \
            acc[2 * _k + 1] = fmaf((vv), _f.y, acc[2 * _k + 1]);              \
        }                                                                     \
    } while (0)

    int i = 0;
    for (; i + 8 <= cnt; i += 8) {
        int2 em[8];
        uint4 q[8];
#pragma unroll
        for (int k = 0; k < 8; k++) em[k] = seg[i + k];
#pragma unroll
        for (int k = 0; k < 8; k++)
            q[k] = __ldg(&sup4[(size_t)em[k].x * 32 + lane]);
#pragma unroll
        for (int k = 0; k < 8; k++)
            ACC_EDGE(q[k], __int_as_float(em[k].y));
    }
    for (; i < cnt; i++) {
        const int2 ee = seg[i];
        const uint4 q = __ldg(&sup4[(size_t)ee.x * 32 + lane]);
        ACC_EDGE(q, __int_as_float(ee.y));
    }
#undef ACC_EDGE

    float4* out4 = reinterpret_cast<float4*>(out);
    out4[(size_t)row * 64 + lane * 2 + 0] =
        make_float4(acc[0], acc[1], acc[2], acc[3]);
    out4[(size_t)row * 64 + lane * 2 + 1] =
        make_float4(acc[4], acc[5], acc[6], acc[7]);
}

// ---------------------------------------------------------------------------
// Launch: R10 topology — CSR on s2; convB + convA + GEMM on main; join; SpMM.
// ---------------------------------------------------------------------------
extern "C" void kernel_launch(void* const* d_in, const int* in_sizes, int n_in,
                              void* d_out, int out_size)
{
    const float* inputs   = (const float*)d_in[0];
    const int*   edge_row = (const int*)  d_in[1];
    const int*   edge_col = (const int*)  d_in[2];
    const float* edge_val = (const float*)d_in[3];
    const float* weight   = (const float*)d_in[4];
    const float* bias     = (const float*)d_in[5];
    float* out = (float*)d_out;

    __half* support = nullptr;
    cudaGetSymbolAddress((void**)&support, g_support);

    static cudaStream_t s2 = nullptr;
    static cudaEvent_t ev_fork = nullptr, ev_join = nullptr;
    static int init_done = 0;
    if (!init_done) {
        cudaStreamCreateWithFlags(&s2, cudaStreamNonBlocking);
        cudaEventCreateWithFlags(&ev_fork, cudaEventDisableTiming);
        cudaEventCreateWithFlags(&ev_join, cudaEventDisableTiming);
        cudaFuncSetAttribute(gemm_fp16_kernel,
                             cudaFuncAttributeMaxDynamicSharedMemorySize, GM_SMEM);
        init_done = 1;
    }

    // Fork.
    cudaEventRecord(ev_fork, 0);
    cudaStreamWaitEvent(s2, ev_fork, 0);

    // s2: padded-CSR build.
    zero_counts_kernel<<<(N_NODES + 255) / 256, 256, 0, s2>>>();
    scatter_kernel<<<(N_EDGES + 255) / 256, 256, 0, s2>>>(edge_row, edge_col, edge_val);
    cudaEventRecord(ev_join, s2);

    // main: B convert + A convert + pure fp16 GEMM.
    convert_B_kernel<<<IN_DIM, 256>>>(weight);
    {
        const int ca_blocks = (int)((CA_TOTAL_F4 + 255) / 256);   // 25024
        convert_A_kernel<<<ca_blocks, 256>>>(inputs);
    }
    {
        int grid = (N_NODES + GM_BM - 1) / GM_BM;   // 391
        gemm_fp16_kernel<<<grid, 512, GM_SMEM>>>(support);
    }

    // Join, then SpMM.
    cudaStreamWaitEvent(0, ev_join, 0);
    spmm_csr_kernel<<<N_NODES / 8, 256>>>(bias, out);
}

// round 16
// speedup vs baseline: 1.0079x; 1.0079x over previous
#include <cuda_runtime.h>
#include <cuda_fp16.h>
#include <mma.h>
#include <cstdint>

using namespace nvcuda;

// Problem constants
#define N_NODES 50000
#define N_EDGES 1600000
#define IN_DIM  512
#define OUT_DIM 256
#define DEG_CAP 128      // P(degree > 128) ~ 0 for Binomial(1.6M, 1/50K)

#define M_PAD   50048    // 391 * 128

// Pre-converted A (inputs) in fp16: [M_PAD, 512] (51.2 MB)
__device__ static __half g_Ah16[(size_t)M_PAD * IN_DIM];

// Scratch: support = inputs @ weight, [N_NODES, OUT_DIM] in FP16 (25.6 MB)
__device__ static __half g_support[(size_t)N_NODES * OUT_DIM];

// Pre-converted B (weight): fp16 (global staging).
#define B_LDM 272
__device__ static __half g_Bh[(size_t)IN_DIM * B_LDM];

// Padded CSR
__device__ static int   g_counts[N_NODES];
__device__ static int2  g_edge[(size_t)N_NODES * DEG_CAP];   // .x=col,.y=val bits

// ---------------------------------------------------------------------------
// cp.async helpers (sm_80+ base PTX)
// ---------------------------------------------------------------------------
__device__ __forceinline__ void cp_async16(void* sptr, const void* gptr) {
    uint32_t s = (uint32_t)__cvta_generic_to_shared(sptr);
    asm volatile("cp.async.cg.shared.global [%0], [%1], 16;" :: "r"(s), "l"(gptr));
}
#define CP_COMMIT()  asm volatile("cp.async.commit_group;" ::: "memory")
#define CP_WAIT(N)   asm volatile("cp.async.wait_group %0;" :: "n"(N) : "memory")

// ---------------------------------------------------------------------------
// A pre-convert: f32 -> fp16, rows >= N_NODES zeroed.
// ---------------------------------------------------------------------------
#define CA_TOTAL_F4 ((size_t)M_PAD * IN_DIM / 4)   // 6,406,144
__global__ __launch_bounds__(256) void convert_A_kernel(const float* __restrict__ A)
{
    const size_t u = (size_t)blockIdx.x * 256 + threadIdx.x;
    if (u >= CA_TOTAL_F4) return;
    const size_t row = u / (IN_DIM / 4);
    uint2 hp = make_uint2(0u, 0u);
    if (row < N_NODES) {
        const float4 v = *reinterpret_cast<const float4*>(A + u * 4);
        __half2 p0 = __floats2half2_rn(v.x, v.y);
        __half2 p1 = __floats2half2_rn(v.z, v.w);
        hp.x = *reinterpret_cast<uint32_t*>(&p0);
        hp.y = *reinterpret_cast<uint32_t*>(&p1);
    }
    *reinterpret_cast<uint2*>(g_Ah16 + u * 4) = hp;
}

// ---------------------------------------------------------------------------
// B pre-convert: f32 -> fp16.
// ---------------------------------------------------------------------------
__global__ __launch_bounds__(256) void convert_B_kernel(const float* __restrict__ B)
{
    const int k = blockIdx.x;
    const int n = threadIdx.x;
    g_Bh[(size_t)k * B_LDM + n] = __float2half_rn(B[(size_t)k * OUT_DIM + n]);
    if (n < B_LDM - OUT_DIM)
        g_Bh[(size_t)k * B_LDM + OUT_DIM + n] = __float2half_rn(0.f);
}

// ---------------------------------------------------------------------------
// GEMM: pure fp16 WMMA, KC=128 (4 chunks, 8 barriers), cp.async double buffer.
// CTA 128x256, 512 threads, warp tile 32x64. 204.8 KB smem, 1 CTA/SM.
// 64 HMMA/warp per compute run -> long latency-hiding runs.
// ---------------------------------------------------------------------------
#define GM_BM    128
#define GM_KC    128
#define GM_NCH   (IN_DIM / GM_KC)       // 4
#define A_LDM    136                    // 272 B row stride (mod 128 = 16)
#define B_SLD    264                    // 528 B row stride (mod 128 = 16)
#define A_ELEMS  (GM_BM * A_LDM)        // 17408 halves / buffer (34816 B)
#define BS_ELEMS (GM_KC * B_SLD)        // 33792 halves / buffer (67584 B)
#define GM_SMEM  ((2 * A_ELEMS + 2 * BS_ELEMS) * 2)   // 204800 B

__global__ __launch_bounds__(512, 1) void gemm_fp16_kernel(
    __half* __restrict__ C)
{
    extern __shared__ __align__(16) char smem[];
    __half* Aring = reinterpret_cast<__half*>(smem);
    __half* Bring = Aring + 2 * A_ELEMS;

    const int tid  = threadIdx.x;
    const int wid  = tid >> 5;
    const int lane = tid & 31;
    const int wm   = wid >> 2;
    const int wn   = wid & 3;
    const int mbase = blockIdx.x * GM_BM;

    wmma::fragment<wmma::accumulator, 16, 16, 16, float> acc[2][4];
#pragma unroll
    for (int i = 0; i < 2; i++)
#pragma unroll
        for (int j = 0; j < 4; j++) wmma::fill_fragment(acc[i][j], 0.0f);

    auto issue_chunk = [&](int ch, int buf) {
        __half* Ab = Aring + buf * A_ELEMS;
        __half* Bb = Bring + buf * BS_ELEMS;
        // A: 128 rows x 16 units(16B) = 2048 units; 4/thread.
#pragma unroll
        for (int it = 0; it < 4; it++) {
            const int u = tid + 512 * it;
            const int r = u >> 4;
            const int c = u & 15;
            cp_async16(Ab + r * A_LDM + c * 8,
                       g_Ah16 + (size_t)(mbase + r) * IN_DIM + ch * GM_KC + c * 8);
        }
        // B: 128 rows x 32 units = 4096 units; 8/thread.
#pragma unroll
        for (int it = 0; it < 8; it++) {
            const int u = tid + 512 * it;
            const int r = u >> 5;
            const int c = u & 31;
            cp_async16(Bb + r * B_SLD + c * 8,
                       g_Bh + (size_t)(ch * GM_KC + r) * B_LDM + c * 8);
        }
    };

    // ---- prologue: chunk 0 in flight ----
    issue_chunk(0, 0); CP_COMMIT();

    for (int ch = 0; ch < GM_NCH; ch++) {
        // issue chunk ch+1 into other buffer (free: compute(ch-1) ended with a barrier)
        const bool more = (ch + 1 < GM_NCH);
        if (more) { issue_chunk(ch + 1, (ch + 1) & 1); CP_COMMIT(); }

        if (more) CP_WAIT(1); else CP_WAIT(0);   // chunk ch resident
        __syncthreads();

        // ---- compute chunk ch: 8 k-steps of 16, 64 HMMA/warp ----
        const __half* Acur = Aring + (ch & 1) * A_ELEMS;
        const __half* Bcur = Bring + (ch & 1) * BS_ELEMS;
#pragma unroll
        for (int ks = 0; ks < GM_KC / 16; ks++) {
            wmma::fragment<wmma::matrix_a, 16, 16, 16, __half, wmma::row_major> ah[2];
#pragma unroll
            for (int i = 0; i < 2; i++) {
                const int ar = wm * 32 + i * 16;
                wmma::load_matrix_sync(ah[i], Acur + ar * A_LDM + ks * 16, A_LDM);
            }
#pragma unroll
            for (int j = 0; j < 4; j++) {
                const int nc = wn * 64 + j * 16;
                wmma::fragment<wmma::matrix_b, 16, 16, 16, __half, wmma::row_major> bf;
                wmma::load_matrix_sync(bf, Bcur + ks * 16 * B_SLD + nc, B_SLD);
#pragma unroll
                for (int i = 0; i < 2; i++)
                    wmma::mma_sync(acc[i][j], ah[i], bf, acc[i][j]);
            }
        }
        __syncthreads();                  // buffer (ch&1) free for ch+2's issue
    }

    // ---- epilogue: stage f32 tiles in smem, convert to fp16, store ----
    float* stage = reinterpret_cast<float*>(smem) + wid * 256;   // 16 KB
    const int lr = lane >> 1;
    const int lc = (lane & 1) * 8;

#pragma unroll
    for (int i = 0; i < 2; i++) {
        const int r0 = mbase + wm * 32 + i * 16;
        const bool ok = (r0 + 16 <= N_NODES);
#pragma unroll
        for (int j = 0; j < 4; j++) {
            wmma::store_matrix_sync(stage, acc[i][j], 16, wmma::mem_row_major);
            __syncwarp();
            if (ok) {
                const int c0 = wn * 64 + j * 16;
                const float* sp = stage + lr * 16 + lc;
                __half2 hh[4];
#pragma unroll
                for (int q = 0; q < 4; q++)
                    hh[q] = __floats2half2_rn(sp[2 * q], sp[2 * q + 1]);
                *reinterpret_cast<uint4*>(
                    &C[(size_t)(r0 + lr) * OUT_DIM + c0 + lc]) =
                    *reinterpret_cast<uint4*>(hh);
            }
            __syncwarp();
        }
    }
}

// ---------------------------------------------------------------------------
// Padded-CSR build (side stream)
// ---------------------------------------------------------------------------
__global__ __launch_bounds__(256) void zero_counts_kernel()
{
    int i = blockIdx.x * 256 + threadIdx.x;
    if (i < N_NODES) g_counts[i] = 0;
}

__global__ __launch_bounds__(256) void scatter_kernel(
    const int* __restrict__ rows,
    const int* __restrict__ cols,
    const float* __restrict__ vals)
{
    int e = blockIdx.x * 256 + threadIdx.x;
    if (e >= N_EDGES) return;
    const int r = rows[e];
    int pos = atomicAdd(&g_counts[r], 1);
    if (pos < DEG_CAP)
        g_edge[(size_t)r * DEG_CAP + pos] = make_int2(cols[e], __float_as_int(vals[e]));
}

// ---------------------------------------------------------------------------
// SpMM over padded CSR, FP16 support gathers, unroll 8 (R10-proven).
// CTA = 256 threads = 8 rows x 32 lanes; lane owns 8 columns (uint4).
// ---------------------------------------------------------------------------
__global__ __launch_bounds__(256) void spmm_csr_kernel(
    const float* __restrict__ bias,
    float* __restrict__ out)
{
    const int g = threadIdx.x >> 5;
    const int lane = threadIdx.x & 31;
    const int row = blockIdx.x * 8 + g;      // 50000 = 8 * 6250

    const int2* __restrict__ seg = g_edge + (size_t)row * DEG_CAP;
    int cnt = g_counts[row];
    if (cnt > DEG_CAP) cnt = DEG_CAP;

    const uint4* __restrict__ sup4 = reinterpret_cast<const uint4*>(g_support);

    float acc[8];
    {
        const float4 b0 = __ldg(reinterpret_cast<const float4*>(bias) + lane * 2);
        const float4 b1 = __ldg(reinterpret_cast<const float4*>(bias) + lane * 2 + 1);
        acc[0] = b0.x; acc[1] = b0.y; acc[2] = b0.z; acc[3] = b0.w;
        acc[4] = b1.x; acc[5] = b1.y; acc[6] = b1.z; acc[7] = b1.w;
    }

#define ACC_EDGE(qv, vv) do {                                                 \
        const __half2* _h = reinterpret_cast<const __half2*>(&(qv));          \
        _Pragma("unroll")                                                     \
        for (int _k = 0; _k < 4; _k++) {                                      \
            const float2 _f = __half22float2(_h[_k]);                         \
            acc[2 * _k + 0] = fmaf((vv), _f.x, acc[2 * _k + 0]);              \
            acc[2 * _k + 1] = fmaf((vv), _f.y, acc[2 * _k + 1]);              \
        }                                                                     \
    } while (0)

    int i = 0;
    for (; i + 8 <= cnt; i += 8) {
        int2 em[8];
        uint4 q[8];
#pragma unroll
        for (int k = 0; k < 8; k++) em[k] = seg[i + k];
#pragma unroll
        for (int k = 0; k < 8; k++)
            q[k] = __ldg(&sup4[(size_t)em[k].x * 32 + lane]);
#pragma unroll
        for (int k = 0; k < 8; k++)
            ACC_EDGE(q[k], __int_as_float(em[k].y));
    }
    for (; i < cnt; i++) {
        const int2 ee = seg[i];
        const uint4 q = __ldg(&sup4[(size_t)ee.x * 32 + lane]);
        ACC_EDGE(q, __int_as_float(ee.y));
    }
#undef ACC_EDGE

    float4* out4 = reinterpret_cast<float4*>(out);
    out4[(size_t)row * 64 + lane * 2 + 0] =
        make_float4(acc[0], acc[1], acc[2], acc[3]);
    out4[(size_t)row * 64 + lane * 2 + 1] =
        make_float4(acc[4], acc[5], acc[6], acc[7]);
}

// ---------------------------------------------------------------------------
// Launch: s2 = convB + CSR build; main = convA + GEMM (waits convB); join; SpMM.
// ---------------------------------------------------------------------------
extern "C" void kernel_launch(void* const* d_in, const int* in_sizes, int n_in,
                              void* d_out, int out_size)
{
    const float* inputs   = (const float*)d_in[0];
    const int*   edge_row = (const int*)  d_in[1];
    const int*   edge_col = (const int*)  d_in[2];
    const float* edge_val = (const float*)d_in[3];
    const float* weight   = (const float*)d_in[4];
    const float* bias     = (const float*)d_in[5];
    float* out = (float*)d_out;

    __half* support = nullptr;
    cudaGetSymbolAddress((void**)&support, g_support);

    static cudaStream_t s2 = nullptr;
    static cudaEvent_t ev_fork = nullptr, ev_b = nullptr, ev_csr = nullptr;
    static int init_done = 0;
    if (!init_done) {
        cudaStreamCreateWithFlags(&s2, cudaStreamNonBlocking);
        cudaEventCreateWithFlags(&ev_fork, cudaEventDisableTiming);
        cudaEventCreateWithFlags(&ev_b,    cudaEventDisableTiming);
        cudaEventCreateWithFlags(&ev_csr,  cudaEventDisableTiming);
        cudaFuncSetAttribute(gemm_fp16_kernel,
                             cudaFuncAttributeMaxDynamicSharedMemorySize, GM_SMEM);
        init_done = 1;
    }

    // Fork.
    cudaEventRecord(ev_fork, 0);
    cudaStreamWaitEvent(s2, ev_fork, 0);

    // s2: B convert, then padded-CSR build.
    convert_B_kernel<<<IN_DIM, 256, 0, s2>>>(weight);
    cudaEventRecord(ev_b, s2);
    zero_counts_kernel<<<(N_NODES + 255) / 256, 256, 0, s2>>>();
    scatter_kernel<<<(N_EDGES + 255) / 256, 256, 0, s2>>>(edge_row, edge_col, edge_val);
    cudaEventRecord(ev_csr, s2);

    // main: A convert (overlaps convB+CSR), then GEMM (needs g_Bh).
    {
        const int ca_blocks = (int)((CA_TOTAL_F4 + 255) / 256);   // 25024
        convert_A_kernel<<<ca_blocks, 256>>>(inputs);
    }
    cudaStreamWaitEvent(0, ev_b, 0);
    {
        int grid = (N_NODES + GM_BM - 1) / GM_BM;   // 391
        gemm_fp16_kernel<<<grid, 512, GM_SMEM>>>(support);
    }

    // Join, then SpMM.
    cudaStreamWaitEvent(0, ev_csr, 0);
    spmm_csr_kernel<<<N_NODES / 8, 256>>>(bias, out);
}

// round 17
// speedup vs baseline: 1.1120x; 1.1032x over previous
#include <cuda_runtime.h>
#include <cuda_fp16.h>
#include <mma.h>
#include <cstdint>

using namespace nvcuda;

// Problem constants
#define N_NODES 50000
#define N_EDGES 1600000
#define IN_DIM  512
#define OUT_DIM 256
#define DEG_CAP 128      // P(degree > 128) ~ 0 for Binomial(1.6M, 1/50K)

// Scratch: support = inputs @ weight, [N_NODES, OUT_DIM] in FP16 (25.6 MB)
__device__ static __half g_support[(size_t)N_NODES * OUT_DIM];

// Pre-converted B (weight): fp16 (global staging).
#define B_LDM 272
__device__ static __half g_Bh[(size_t)IN_DIM * B_LDM];

// Padded CSR
__device__ static int   g_counts[N_NODES];
__device__ static int2  g_edge[(size_t)N_NODES * DEG_CAP];   // .x=col,.y=val bits

// ---------------------------------------------------------------------------
// cp.async helpers (sm_80+ base PTX)
// ---------------------------------------------------------------------------
__device__ __forceinline__ void cp_async16(void* sptr, const void* gptr) {
    uint32_t s = (uint32_t)__cvta_generic_to_shared(sptr);
    asm volatile("cp.async.cg.shared.global [%0], [%1], 16;" :: "r"(s), "l"(gptr));
}
#define CP_COMMIT()  asm volatile("cp.async.commit_group;" ::: "memory")
#define CP_WAIT(N)   asm volatile("cp.async.wait_group %0;" :: "n"(N) : "memory")

// ---------------------------------------------------------------------------
// B pre-convert: f32 -> fp16.
// ---------------------------------------------------------------------------
__global__ __launch_bounds__(256) void convert_B_kernel(const float* __restrict__ B)
{
    const int k = blockIdx.x;
    const int n = threadIdx.x;
    g_Bh[(size_t)k * B_LDM + n] = __float2half_rn(B[(size_t)k * OUT_DIM + n]);
    if (n < B_LDM - OUT_DIM)
        g_Bh[(size_t)k * B_LDM + OUT_DIM + n] = __float2half_rn(0.f);
}

// ---------------------------------------------------------------------------
// GEMM: WMMA fp16, HIGH OCCUPANCY variant.
// CTA 64x256, 512 threads (16 warps = 4m x 4n), warp tile 16x64 (acc = 32 regs).
// __launch_bounds__(512, 2) forces <=64 regs -> 2 CTAs/SM = 32 warps/SM.
// A: single smem buffer, LDG f32 -> cvt -> STS at loop head (latency hidden by
//    the co-resident CTA, not by register prefetch).
// B: cp.async double buffer. KC=64, 8 chunks. 77 KB smem/CTA.
// ---------------------------------------------------------------------------
#define GM_BM    64
#define GM_KC    64
#define GM_NCH   (IN_DIM / GM_KC)       // 8
#define A_LDM    72                     // 144 B row stride (mod 128 = 16)
#define B_SLD    264                    // 528 B row stride (mod 128 = 16)
#define A_ELEMS  (GM_BM * A_LDM)        // 4608 halves (9216 B)
#define BS_ELEMS (GM_KC * B_SLD)        // 16896 halves (33792 B)
#define GM_SMEM  ((A_ELEMS + 2 * BS_ELEMS) * 2)   // 76800 B/CTA

__global__ __launch_bounds__(512, 2) void gemm_wmma_kernel(
    const float* __restrict__ A,
    __half* __restrict__ C)
{
    extern __shared__ __align__(16) char smem[];
    __half* Ah = reinterpret_cast<__half*>(smem);
    __half* Bs[2] = { Ah + A_ELEMS, Ah + A_ELEMS + BS_ELEMS };

    const int tid  = threadIdx.x;
    const int wid  = tid >> 5;
    const int lane = tid & 31;
    const int wm   = wid >> 2;            // 0..3: 16-row block
    const int wn   = wid & 3;             // 0..3: 64-col block
    const int mbase = blockIdx.x * GM_BM;

    wmma::fragment<wmma::accumulator, 16, 16, 16, float> acc[4];
#pragma unroll
    for (int j = 0; j < 4; j++) wmma::fill_fragment(acc[j], 0.0f);

    // B: 64 rows x 32 uint4 = 2048 units; 4/thread.
    auto issue_B = [&](int ch, int buf) {
#pragma unroll
        for (int it = 0; it < 4; it++) {
            const int u = tid + 512 * it;
            const int r = u >> 5;
            const int c = u & 31;
            cp_async16(Bs[buf] + r * B_SLD + c * 8,
                       g_Bh + (size_t)(ch * GM_KC + r) * B_LDM + c * 8);
        }
    };

    // ---- prologue: B chunk 0 in flight ----
    issue_B(0, 0); CP_COMMIT();

    for (int ch = 0; ch < GM_NCH; ch++) {
        // ---- A chunk ch: LDG f32 -> cvt -> STS (no persistent regs) ----
        // 64 rows x 16 float4 = 1024 float4; 2/thread.
#pragma unroll
        for (int it = 0; it < 2; it++) {
            const int u = tid + 512 * it;
            const int row = u >> 4;            // 0..63
            const int f4  = u & 15;            // 0..15
            const int g = mbase + row;
            float4 v = make_float4(0.f, 0.f, 0.f, 0.f);
            if (g < N_NODES)
                v = *reinterpret_cast<const float4*>(
                    &A[(size_t)g * IN_DIM + ch * GM_KC + f4 * 4]);
            __half2 p0 = __floats2half2_rn(v.x, v.y);
            __half2 p1 = __floats2half2_rn(v.z, v.w);
            uint2 hp;
            hp.x = *reinterpret_cast<uint32_t*>(&p0);
            hp.y = *reinterpret_cast<uint32_t*>(&p1);
            *reinterpret_cast<uint2*>(Ah + row * A_LDM + f4 * 4) = hp;
        }

        // issue next B chunk
        const bool more = (ch + 1 < GM_NCH);
        if (more) { issue_B(ch + 1, (ch + 1) & 1); CP_COMMIT(); }

        if (more) CP_WAIT(1); else CP_WAIT(0);   // B(ch) resident
        __syncthreads();                          // A STS visible

        // ---- compute chunk ch: 4 k-steps, 4 MMA each ----
        const __half* Bcur = Bs[ch & 1];
#pragma unroll
        for (int ks = 0; ks < GM_KC / 16; ks++) {
            wmma::fragment<wmma::matrix_a, 16, 16, 16, __half, wmma::row_major> ah;
            wmma::load_matrix_sync(ah, Ah + (wm * 16) * A_LDM + ks * 16, A_LDM);
#pragma unroll
            for (int j = 0; j < 4; j++) {
                const int nc = wn * 64 + j * 16;
                wmma::fragment<wmma::matrix_b, 16, 16, 16, __half, wmma::row_major> bf;
                wmma::load_matrix_sync(bf, Bcur + ks * 16 * B_SLD + nc, B_SLD);
                wmma::mma_sync(acc[j], ah, bf, acc[j]);
            }
        }
        __syncthreads();                          // A buffer reusable
    }

    // ---- epilogue: stage f32 tiles in smem, convert to fp16, store ----
    float* stage = reinterpret_cast<float*>(smem) + wid * 256;   // 16 KB
    const int lr = lane >> 1;
    const int lc = (lane & 1) * 8;

    const int r0 = mbase + wm * 16;
    const bool ok = (r0 + 16 <= N_NODES);
#pragma unroll
    for (int j = 0; j < 4; j++) {
        wmma::store_matrix_sync(stage, acc[j], 16, wmma::mem_row_major);
        __syncwarp();
        if (ok) {
            const int c0 = wn * 64 + j * 16;
            const float* sp = stage + lr * 16 + lc;
            __half2 hh[4];
#pragma unroll
            for (int q = 0; q < 4; q++)
                hh[q] = __floats2half2_rn(sp[2 * q], sp[2 * q + 1]);
            *reinterpret_cast<uint4*>(
                &C[(size_t)(r0 + lr) * OUT_DIM + c0 + lc]) =
                *reinterpret_cast<uint4*>(hh);
        }
        __syncwarp();
    }
}

// ---------------------------------------------------------------------------
// Padded-CSR build (side stream)
// ---------------------------------------------------------------------------
__global__ __launch_bounds__(256) void zero_counts_kernel()
{
    int i = blockIdx.x * 256 + threadIdx.x;
    if (i < N_NODES) g_counts[i] = 0;
}

__global__ __launch_bounds__(256) void scatter_kernel(
    const int* __restrict__ rows,
    const int* __restrict__ cols,
    const float* __restrict__ vals)
{
    int e = blockIdx.x * 256 + threadIdx.x;
    if (e >= N_EDGES) return;
    const int r = rows[e];
    int pos = atomicAdd(&g_counts[r], 1);
    if (pos < DEG_CAP)
        g_edge[(size_t)r * DEG_CAP + pos] = make_int2(cols[e], __float_as_int(vals[e]));
}

// ---------------------------------------------------------------------------
// SpMM over padded CSR, FP16 support gathers, unroll 8 (R10-proven).
// CTA = 256 threads = 8 rows x 32 lanes; lane owns 8 columns (uint4).
// ---------------------------------------------------------------------------
__global__ __launch_bounds__(256) void spmm_csr_kernel(
    const float* __restrict__ bias,
    float* __restrict__ out)
{
    const int g = threadIdx.x >> 5;
    const int lane = threadIdx.x & 31;
    const int row = blockIdx.x * 8 + g;      // 50000 = 8 * 6250

    const int2* __restrict__ seg = g_edge + (size_t)row * DEG_CAP;
    int cnt = g_counts[row];
    if (cnt > DEG_CAP) cnt = DEG_CAP;

    const uint4* __restrict__ sup4 = reinterpret_cast<const uint4*>(g_support);

    float acc[8];
    {
        const float4 b0 = __ldg(reinterpret_cast<const float4*>(bias) + lane * 2);
        const float4 b1 = __ldg(reinterpret_cast<const float4*>(bias) + lane * 2 + 1);
        acc[0] = b0.x; acc[1] = b0.y; acc[2] = b0.z; acc[3] = b0.w;
        acc[4] = b1.x; acc[5] = b1.y; acc[6] = b1.z; acc[7] = b1.w;
    }

#define ACC_EDGE(qv, vv) do {                                                 \
        const __half2* _h = reinterpret_cast<const __half2*>(&(qv));          \
        _Pragma("unroll")                                                     \
        for (int _k = 0; _k < 4; _k++) {                                      \
            const float2 _f = __half22float2(_h[_k]);                         \
            acc[2 * _k + 0] = fmaf((vv), _f.x, acc[2 * _k + 0]);              \
            acc[2 * _k + 1] = fmaf((vv), _f.y, acc[2 * _k + 1]);              \
        }                                                                     \
    } while (0)

    int i = 0;
    for (; i + 8 <= cnt; i += 8) {
        int2 em[8];
        uint4 q[8];
#pragma unroll
        for (int k = 0; k < 8; k++) em[k] = seg[i + k];
#pragma unroll
        for (int k = 0; k < 8; k++)
            q[k] = __ldg(&sup4[(size_t)em[k].x * 32 + lane]);
#pragma unroll
        for (int k = 0; k < 8; k++)
            ACC_EDGE(q[k], __int_as_float(em[k].y));
    }
    for (; i < cnt; i++) {
        const int2 ee = seg[i];
        const uint4 q = __ldg(&sup4[(size_t)ee.x * 32 + lane]);
        ACC_EDGE(q, __int_as_float(ee.y));
    }
#undef ACC_EDGE

    float4* out4 = reinterpret_cast<float4*>(out);
    out4[(size_t)row * 64 + lane * 2 + 0] =
        make_float4(acc[0], acc[1], acc[2], acc[3]);
    out4[(size_t)row * 64 + lane * 2 + 1] =
        make_float4(acc[4], acc[5], acc[6], acc[7]);
}

// ---------------------------------------------------------------------------
// Launch: R10 topology — CSR on s2; convB + GEMM on main; join; SpMM.
// ---------------------------------------------------------------------------
extern "C" void kernel_launch(void* const* d_in, const int* in_sizes, int n_in,
                              void* d_out, int out_size)
{
    const float* inputs   = (const float*)d_in[0];
    const int*   edge_row = (const int*)  d_in[1];
    const int*   edge_col = (const int*)  d_in[2];
    const float* edge_val = (const float*)d_in[3];
    const float* weight   = (const float*)d_in[4];
    const float* bias     = (const float*)d_in[5];
    float* out = (float*)d_out;

    __half* support = nullptr;
    cudaGetSymbolAddress((void**)&support, g_support);

    static cudaStream_t s2 = nullptr;
    static cudaEvent_t ev_fork = nullptr, ev_join = nullptr;
    static int init_done = 0;
    if (!init_done) {
        cudaStreamCreateWithFlags(&s2, cudaStreamNonBlocking);
        cudaEventCreateWithFlags(&ev_fork, cudaEventDisableTiming);
        cudaEventCreateWithFlags(&ev_join, cudaEventDisableTiming);
        cudaFuncSetAttribute(gemm_wmma_kernel,
                             cudaFuncAttributeMaxDynamicSharedMemorySize, GM_SMEM);
        init_done = 1;
    }

    // Fork.
    cudaEventRecord(ev_fork, 0);
    cudaStreamWaitEvent(s2, ev_fork, 0);

    // s2: padded-CSR build.
    zero_counts_kernel<<<(N_NODES + 255) / 256, 256, 0, s2>>>();
    scatter_kernel<<<(N_EDGES + 255) / 256, 256, 0, s2>>>(edge_row, edge_col, edge_val);
    cudaEventRecord(ev_join, s2);

    // main: B convert + high-occupancy GEMM.
    convert_B_kernel<<<IN_DIM, 256>>>(weight);
    {
        int grid = (N_NODES + GM_BM - 1) / GM_BM;   // 782
        gemm_wmma_kernel<<<grid, 512, GM_SMEM>>>(inputs, support);
    }

    // Join, then SpMM.
    cudaStreamWaitEvent(0, ev_join, 0);
    spmm_csr_kernel<<<N_NODES / 8, 256>>>(bias, out);
}